// round 15
// baseline (speedup 1.0000x reference)
#include <cuda_runtime.h>
#include <cstdint>
#include <math.h>

#define NN      100000
#define IN_DIM  512
#define OUT_DIM 128
#define HW_GRID 1024                 // hist+wf fused grid (resident: 8/SM x 148)

// ---------------------------------------------------------------------------
// Scratch. g_zero cleared by one memset per call:
//   [0,2NN) int deg | 1024 f wf | 256 f cpre | 4 int bar | acc float2 x 2NN
// ---------------------------------------------------------------------------
#define OFF_WF   (2 * NN)
#define OFF_CPRE (2 * NN + 1024)
#define OFF_BAR  (2 * NN + 1024 + 256)
#define OFF_ACC  (2 * NN + 1024 + 256 + 4)      // 8B aligned
#define ZERO_INTS (OFF_ACC + 4 * NN)
__device__ __align__(16) int g_zero[ZERO_INTS];
__device__ float  g_v [2 * OUT_DIM];
__device__ float  g_u [2 * IN_DIM];
__device__ float  g_k [2];
__device__ float4 g_p4[NN];                      // (pfa, pfb, psa, psb)

// ---------------------------------------------------------------------------
// Grid barrier (counter pre-zeroed by memset)
// ---------------------------------------------------------------------------
__device__ __forceinline__ void grid_bar(int* cnt, int nblocks) {
    __threadfence();
    __syncthreads();
    if (threadIdx.x == 0) {
        atomicAdd(cnt, 1);
        while (*(volatile int*)cnt < nblocks) {}
    }
    __syncthreads();
}

// ---------------------------------------------------------------------------
// Vector reduction: addr[0] += a, addr[1] += b
// ---------------------------------------------------------------------------
__device__ __forceinline__ void red_v2(float2* addr, float a, float b) {
    asm volatile("red.global.add.v2.f32 [%0], {%1, %2};"
                 :: "l"(addr), "f"(a), "f"(b) : "memory");
}

// ---------------------------------------------------------------------------
// Fused hist + wf: one resident grid, one barrier. Saves a kernel boundary.
//   Phase A: out-degree histograms over both src lists (grid-stride).
//   Phase B: wf[c] = sum_v deg1[v]*feat[v,c] ; wf[512+c] = ... deg2 ...
// ---------------------------------------------------------------------------
__global__ __launch_bounds__(256, 8) void histwf_kernel(
    const float* __restrict__ feat,
    const int* __restrict__ src1, int ne1,
    const int* __restrict__ src2, int ne2,
    int* __restrict__ deg, float* __restrict__ wf,
    int* __restrict__ bar, int n)
{
    __shared__ float red[256 * 8];
    const int t = threadIdx.x;
    const int gtid = blockIdx.x * 256 + t;
    const int GSZ = gridDim.x * 256;

    cudaGridDependencySynchronize();             // PDL: wait on memset

    // ---- phase A: histograms --------------------------------------------
    {
        int nq = (ne1 + 3) >> 2;
        for (int q = gtid; q < nq; q += GSZ) {
            int e0 = q * 4;
            if (e0 + 3 < ne1) {
                int4 s = *(const int4*)(src1 + e0);
                atomicAdd(&deg[s.x], 1);
                atomicAdd(&deg[s.y], 1);
                atomicAdd(&deg[s.z], 1);
                atomicAdd(&deg[s.w], 1);
            } else {
                for (int e = e0; e < ne1; e++) atomicAdd(&deg[src1[e]], 1);
            }
        }
        int* dg = deg + NN;
        nq = (ne2 + 3) >> 2;
        for (int q = gtid; q < nq; q += GSZ) {
            int e0 = q * 4;
            if (e0 + 3 < ne2) {
                int4 s = *(const int4*)(src2 + e0);
                atomicAdd(&dg[s.x], 1);
                atomicAdd(&dg[s.y], 1);
                atomicAdd(&dg[s.z], 1);
                atomicAdd(&dg[s.w], 1);
            } else {
                for (int e = e0; e < ne2; e++) atomicAdd(&dg[src2[e]], 1);
            }
        }
    }
    grid_bar(&bar[2], gridDim.x);

    // ---- phase B: wf ------------------------------------------------------
    {
        int half = t >> 7, c = t & 127;
        const float4* f4 = (const float4*)feat;
        const int* d1 = deg;
        const int* d2 = deg + NN;
        float4 a1 = make_float4(0.f, 0.f, 0.f, 0.f);
        float4 a2 = make_float4(0.f, 0.f, 0.f, 0.f);
        for (int v = blockIdx.x * 2 + half; v < n; v += gridDim.x * 2) {
            float w1 = (float)__ldcg(&d1[v]);    // atomics wrote L2
            float w2 = (float)__ldcg(&d2[v]);
            float4 x = __ldg(&f4[(size_t)v * 128 + c]);
            a1.x += w1 * x.x; a1.y += w1 * x.y; a1.z += w1 * x.z; a1.w += w1 * x.w;
            a2.x += w2 * x.x; a2.y += w2 * x.y; a2.z += w2 * x.z; a2.w += w2 * x.w;
        }
        *(float4*)&red[t * 8]     = a1;
        *(float4*)&red[t * 8 + 4] = a2;
        __syncthreads();
        if (half == 0) {
            int p = (t + 128) * 8;
            a1.x += red[p];     a1.y += red[p + 1];
            a1.z += red[p + 2]; a1.w += red[p + 3];
            a2.x += red[p + 4]; a2.y += red[p + 5];
            a2.z += red[p + 6]; a2.w += red[p + 7];
            atomicAdd(&wf[c * 4],     a1.x);
            atomicAdd(&wf[c * 4 + 1], a1.y);
            atomicAdd(&wf[c * 4 + 2], a1.z);
            atomicAdd(&wf[c * 4 + 3], a1.w);
            atomicAdd(&wf[IN_DIM + c * 4],     a2.x);
            atomicAdd(&wf[IN_DIM + c * 4 + 1], a2.y);
            atomicAdd(&wf[IN_DIM + c * 4 + 2], a2.z);
            atomicAdd(&wf[IN_DIM + c * 4 + 3], a2.w);
        }
    }
}

// ---------------------------------------------------------------------------
// Fused small chain: cpre -> v -> u, kc (grid barriers). 128 blocks x 128.
// ---------------------------------------------------------------------------
__global__ __launch_bounds__(128) void chain_kernel(
    const float* __restrict__ W1, const float* __restrict__ W2,
    const float* __restrict__ Wb, const float* __restrict__ b1,
    const float* __restrict__ b2, const float* __restrict__ bb,
    const float* __restrict__ wf, float* __restrict__ cpre,
    float* __restrict__ v, float* __restrict__ u, float* __restrict__ kc,
    int* __restrict__ bar, float inv_n)
{
    cudaGridDependencySynchronize();             // PDL: wait on histwf
    int b = blockIdx.x;          // 0..127
    int t = threadIdx.x;         // 0..127
    int warp = t >> 5, lane = t & 31;

    {
        int hh = b >> 6, chunk = b & 63;
        const float* W = hh ? W2 : W1;
        const float* w = wf + hh * IN_DIM + chunk * 8;
        const float* Wc = W + (size_t)(chunk * 8) * OUT_DIM + t;
        float s = 0.f;
        #pragma unroll
        for (int k = 0; k < 8; k++)
            s += __ldg(&w[k]) * __ldg(&Wc[k * OUT_DIM]);
        atomicAdd(&cpre[hh * OUT_DIM + t], s);
    }
    grid_bar(&bar[0], 128);

    if (b < 64) {
        int gw = b * 4 + warp;
        int half = gw >> 7, d = gw & 127;
        const float* bh = half ? b2 : b1;
        const float* cp = cpre + half * OUT_DIM;
        const float* wr = Wb + (size_t)d * OUT_DIM;
        float s = 0.f;
        #pragma unroll
        for (int j = 0; j < 4; j++) {
            int e = lane + 32 * j;
            float c = 1.0f / (1.0f + expf(-(__ldcg(&cp[e]) * inv_n + __ldg(&bh[e]))));
            s += __ldg(&wr[e]) * c;
        }
        #pragma unroll
        for (int o = 16; o; o >>= 1) s += __shfl_xor_sync(0xffffffffu, s, o);
        if (lane == 0) v[half * OUT_DIM + d] = s;
    }
    grid_bar(&bar[1], 128);

    int W512 = b * 4 + warp;     // 0..511
    #pragma unroll
    for (int rep = 0; rep < 2; rep++) {
        int idx = W512 + rep * 512;
        int half = idx >> 9;                 // 0: u_a (W2,v1)  1: u_b (W1,v2)
        int tt = idx & 511;
        const float* W = half ? W1 : W2;
        const float* vv = v + half * OUT_DIM;
        const float* wr = W + (size_t)tt * OUT_DIM;
        float s = 0.f;
        #pragma unroll
        for (int j = 0; j < 4; j++) {
            int d = lane + 32 * j;
            s += __ldg(&wr[d]) * __ldcg(&vv[d]);
        }
        #pragma unroll
        for (int o = 16; o; o >>= 1) s += __shfl_xor_sync(0xffffffffu, s, o);
        if (lane == 0) u[half * IN_DIM + tt] = s;
    }
    if (W512 < 2) {                          // kc[0]=b2.v1+bb, kc[1]=b1.v2+bb
        const float* bv = W512 ? b1 : b2;
        const float* vv = v + W512 * OUT_DIM;
        float s = 0.f;
        #pragma unroll
        for (int j = 0; j < 4; j++) {
            int d = lane + 32 * j;
            s += __ldg(&bv[d]) * __ldcg(&vv[d]);
        }
        #pragma unroll
        for (int o = 16; o; o >>= 1) s += __shfl_xor_sync(0xffffffffu, s, o);
        if (lane == 0) kc[W512] = s + __ldg(bb);
    }
}

// ---------------------------------------------------------------------------
// p GEMVs over feat and shuf, writing interleaved p4 = (pfa,pfb,psa,psb).
// ---------------------------------------------------------------------------
__global__ __launch_bounds__(512) void p_both_kernel(
    const float* __restrict__ feat, const float* __restrict__ shuf,
    const float* __restrict__ u, float4* __restrict__ p4, int n)
{
    __shared__ __align__(16) float su[2 * IN_DIM];
    cudaGridDependencySynchronize();             // PDL: wait on chain (u)
    for (int i = threadIdx.x; i < 2 * IN_DIM; i += 512) su[i] = u[i];
    __syncthreads();

    int warp = threadIdx.x >> 5, lane = threadIdx.x & 31;
    int idx = blockIdx.x * 16 + warp;          // 0 .. 2n-1
    if (idx >= 2 * n) return;
    const float* X;
    int v;
    int is_shuf;
    if (idx < n) { X = feat; v = idx;     is_shuf = 0; }
    else         { X = shuf; v = idx - n; is_shuf = 1; }

    const float4* x4 = (const float4*)(X + (size_t)v * IN_DIM);
    const float4* ua4 = (const float4*)su;
    const float4* ub4 = (const float4*)(su + IN_DIM);
    float sa = 0.f, sb = 0.f;
    #pragma unroll
    for (int j = 0; j < 4; j++) {
        float4 x = x4[lane + 32 * j];
        float4 a = ua4[lane + 32 * j];
        float4 b = ub4[lane + 32 * j];
        sa += x.x * a.x + x.y * a.y + x.z * a.z + x.w * a.w;
        sb += x.x * b.x + x.y * b.y + x.z * b.z + x.w * b.w;
    }
    #pragma unroll
    for (int o = 16; o; o >>= 1) {
        sa += __shfl_xor_sync(0xffffffffu, sa, o);
        sb += __shfl_xor_sync(0xffffffffu, sb, o);
    }
    if (lane == 0) {
        float2* dst = (float2*)&p4[v] + is_shuf;   // .xy or .zw
        *dst = make_float2(sa, sb);
    }
}

// ---------------------------------------------------------------------------
// Scatter with v2 reductions.
//   blockIdx.y 0: list2 -> accA (q0,q2) ;  1: list1 -> accB (q1,q3)
// ---------------------------------------------------------------------------
__global__ __launch_bounds__(256) void scatter_v2_kernel(
    const int* __restrict__ src2, const int* __restrict__ dst2, int ne2,
    const int* __restrict__ src1, const int* __restrict__ dst1, int ne1,
    const float4* __restrict__ p4, float2* __restrict__ accA,
    float2* __restrict__ accB)
{
    cudaGridDependencySynchronize();             // PDL: wait on p
    const int* src; const int* dst; float2* acc; int ne; int sel;
    if (blockIdx.y == 0) { src = src2; dst = dst2; ne = ne2; acc = accA; sel = 0; }
    else                 { src = src1; dst = dst1; ne = ne1; acc = accB; sel = 1; }

    int e0 = (blockIdx.x * 256 + threadIdx.x) * 4;
    if (e0 + 3 < ne) {
        int4 s = *(const int4*)(src + e0);
        int4 d = *(const int4*)(dst + e0);
        float4 px = __ldg(&p4[s.x]);
        float4 py = __ldg(&p4[s.y]);
        float4 pz = __ldg(&p4[s.z]);
        float4 pw = __ldg(&p4[s.w]);
        if (sel == 0) {
            red_v2(&acc[d.x], px.x, px.z);
            red_v2(&acc[d.y], py.x, py.z);
            red_v2(&acc[d.z], pz.x, pz.z);
            red_v2(&acc[d.w], pw.x, pw.z);
        } else {
            red_v2(&acc[d.x], px.y, px.w);
            red_v2(&acc[d.y], py.y, py.w);
            red_v2(&acc[d.z], pz.y, pz.w);
            red_v2(&acc[d.w], pw.y, pw.w);
        }
    } else {
        for (int e = e0; e < ne; e++) {
            float4 pv = __ldg(&p4[src[e]]);
            if (sel == 0) red_v2(&acc[dst[e]], pv.x, pv.z);
            else          red_v2(&acc[dst[e]], pv.y, pv.w);
        }
    }
}

// ---------------------------------------------------------------------------
// Finalize: de-interleave acc into the four output quarters, add constants.
// ---------------------------------------------------------------------------
__global__ void finalize_kernel(const float2* __restrict__ accA,
                                const float2* __restrict__ accB,
                                const float* __restrict__ kc,
                                float* __restrict__ out, int n)
{
    cudaGridDependencySynchronize();             // PDL: wait on scatter
    int i = blockIdx.x * 256 + threadIdx.x;
    if (i < n) {
        float k1 = __ldg(&kc[0]), k2 = __ldg(&kc[1]);
        float2 a = accA[i];
        float2 b = accB[i];
        out[i]         = a.x + k1;   // sc1 = h2.v1
        out[n + i]     = b.x + k2;   // sc2 = h1.v2
        out[2 * n + i] = a.y + k1;   // sc3 = h4.v1
        out[3 * n + i] = b.y + k2;   // sc4 = h3.v2
    }
}

// ---------------------------------------------------------------------------
// PDL launch helper
// ---------------------------------------------------------------------------
template <typename K, typename... Args>
static void launch_pdl(dim3 grid, dim3 block, K kernel, Args... args)
{
    cudaLaunchConfig_t cfg = {};
    cfg.gridDim = grid;
    cfg.blockDim = block;
    cudaLaunchAttribute attr[1];
    attr[0].id = cudaLaunchAttributeProgrammaticStreamSerialization;
    attr[0].val.programmaticStreamSerializationAllowed = 1;
    cfg.attrs = attr;
    cfg.numAttrs = 1;
    cudaLaunchKernelEx(&cfg, kernel, args...);
}

// ---------------------------------------------------------------------------
// Launch
// ---------------------------------------------------------------------------
extern "C" void kernel_launch(void* const* d_in, const int* in_sizes, int n_in,
                              void* d_out, int out_size)
{
    const float* feat = (const float*)d_in[0];
    const float* shuf = (const float*)d_in[1];
    const int*   src1 = (const int*)d_in[2];
    const int*   dst1 = (const int*)d_in[3];
    const int*   src2 = (const int*)d_in[4];
    const int*   dst2 = (const int*)d_in[5];
    const float* W1   = (const float*)d_in[6];
    const float* b1   = (const float*)d_in[7];
    const float* W2   = (const float*)d_in[8];
    const float* b2   = (const float*)d_in[9];
    const float* Wb   = (const float*)d_in[10];
    const float* bb   = (const float*)d_in[11];
    float* out = (float*)d_out;

    const int n   = in_sizes[0] / IN_DIM;   // 100000
    const int ne1 = in_sizes[2];
    const int ne2 = in_sizes[4];

    void* p;
    cudaGetSymbolAddress(&p, g_zero);
    int*    deg  = (int*)p;
    float*  wf   = (float*)((int*)p + OFF_WF);
    float*  cpre = (float*)((int*)p + OFF_CPRE);
    int*    bar  = (int*)p + OFF_BAR;
    float2* accA = (float2*)((int*)p + OFF_ACC);
    float2* accB = accA + NN;
    cudaGetSymbolAddress(&p, g_v);  float* v  = (float*)p;
    cudaGetSymbolAddress(&p, g_u);  float* u  = (float*)p;
    cudaGetSymbolAddress(&p, g_k);  float* kc = (float*)p;
    cudaGetSymbolAddress(&p, g_p4); float4* p4 = (float4*)p;

    // 0) zero deg+wf+cpre+bar+acc (one ~2.4MB memset)
    cudaMemsetAsync(deg, 0, (size_t)ZERO_INTS * sizeof(int));

    // 1) fused histograms + weighted row-sums (one resident grid, 1 barrier)
    launch_pdl(dim3(HW_GRID), dim3(256), histwf_kernel,
               feat, src1, ne1, src2, ne2, deg, wf, bar, n);

    // 2) fused tiny chain -> u, kc
    launch_pdl(dim3(128), dim3(128), chain_kernel,
               W1, W2, Wb, b1, b2, bb, wf, cpre, v, u, kc, bar,
               1.0f / (float)n);

    // 3) p projections for feat+shuf, interleaved p4
    launch_pdl(dim3((2 * n + 15) / 16), dim3(512), p_both_kernel,
               feat, shuf, u, p4, n);

    // 4) scatter with v2 reductions (both lists, one launch)
    int gp1 = (ne1 / 4 + 255) / 256, gp2 = (ne2 / 4 + 255) / 256;
    int gpm = gp1 > gp2 ? gp1 : gp2;
    launch_pdl(dim3(gpm, 2), dim3(256), scatter_v2_kernel,
               src2, dst2, ne2, src1, dst1, ne1, p4, accA, accB);

    // 5) finalize: acc + k -> out quarters
    launch_pdl(dim3((n + 255) / 256), dim3(256), finalize_kernel,
               accA, accB, kc, out, n);
}

// round 16
// speedup vs baseline: 1.0917x; 1.0917x over previous
#include <cuda_runtime.h>
#include <cstdint>
#include <math.h>

#define NN      100000
#define IN_DIM  512
#define OUT_DIM 128

// ---------------------------------------------------------------------------
// Scratch. g_zero cleared by one memset per call:
//   [0,2NN) int deg | 1024 f wf | 256 f cpre | 4 int bar | acc float2 x 2NN
// ---------------------------------------------------------------------------
#define OFF_WF   (2 * NN)
#define OFF_CPRE (2 * NN + 1024)
#define OFF_BAR  (2 * NN + 1024 + 256)
#define OFF_ACC  (2 * NN + 1024 + 256 + 4)      // 8B aligned
#define ZERO_INTS (OFF_ACC + 4 * NN)
__device__ __align__(16) int g_zero[ZERO_INTS];
__device__ float  g_v [2 * OUT_DIM];
__device__ float  g_u [2 * IN_DIM];
__device__ float  g_k [2];
__device__ float4 g_p4[NN];                      // (pfa, pfb, psa, psb)

// ---------------------------------------------------------------------------
// Grid barrier (counter pre-zeroed by memset)
// ---------------------------------------------------------------------------
__device__ __forceinline__ void grid_bar(int* cnt, int nblocks) {
    __threadfence();
    __syncthreads();
    if (threadIdx.x == 0) {
        atomicAdd(cnt, 1);
        while (*(volatile int*)cnt < nblocks) {}
    }
    __syncthreads();
}

// ---------------------------------------------------------------------------
// Vector reduction: addr[0] += a, addr[1] += b
// ---------------------------------------------------------------------------
__device__ __forceinline__ void red_v2(float2* addr, float a, float b) {
    asm volatile("red.global.add.v2.f32 [%0], {%1, %2};"
                 :: "l"(addr), "f"(a), "f"(b) : "memory");
}

// ---------------------------------------------------------------------------
// Histogram over both src lists (blockIdx.y selects list).
// ---------------------------------------------------------------------------
__global__ void hist_both(const int* __restrict__ srcA, int neA,
                          const int* __restrict__ srcB, int neB,
                          int* __restrict__ deg)
{
    cudaGridDependencySynchronize();             // PDL: wait on memset
    const int* src = blockIdx.y ? srcB : srcA;
    int ne = blockIdx.y ? neB : neA;
    int* dg = deg + blockIdx.y * NN;
    int e0 = (blockIdx.x * blockDim.x + threadIdx.x) * 4;
    if (e0 + 3 < ne) {
        int4 s = *(const int4*)(src + e0);
        atomicAdd(&dg[s.x], 1);
        atomicAdd(&dg[s.y], 1);
        atomicAdd(&dg[s.z], 1);
        atomicAdd(&dg[s.w], 1);
    } else {
        for (int e = e0; e < ne; e++) atomicAdd(&dg[src[e]], 1);
    }
}

// ---------------------------------------------------------------------------
// wf[c] = sum_v deg1[v]*feat[v,c] ; wf[512+c] = sum_v deg2[v]*feat[v,c]
// ---------------------------------------------------------------------------
__global__ __launch_bounds__(256) void wf_kernel(
    const float* __restrict__ feat, const int* __restrict__ deg1,
    const int* __restrict__ deg2, float* __restrict__ wf, int n)
{
    __shared__ float red[256 * 8];
    cudaGridDependencySynchronize();             // PDL: wait on hist
    int t = threadIdx.x;
    int half = t >> 7, c = t & 127;
    const float4* f4 = (const float4*)feat;

    float4 a1 = make_float4(0.f, 0.f, 0.f, 0.f);
    float4 a2 = make_float4(0.f, 0.f, 0.f, 0.f);
    for (int v = blockIdx.x * 2 + half; v < n; v += gridDim.x * 2) {
        float w1 = (float)__ldg(&deg1[v]);
        float w2 = (float)__ldg(&deg2[v]);
        float4 x = __ldg(&f4[(size_t)v * 128 + c]);
        a1.x += w1 * x.x; a1.y += w1 * x.y; a1.z += w1 * x.z; a1.w += w1 * x.w;
        a2.x += w2 * x.x; a2.y += w2 * x.y; a2.z += w2 * x.z; a2.w += w2 * x.w;
    }
    *(float4*)&red[t * 8]     = a1;
    *(float4*)&red[t * 8 + 4] = a2;
    __syncthreads();
    if (half == 0) {
        int p = (t + 128) * 8;
        a1.x += red[p];     a1.y += red[p + 1]; a1.z += red[p + 2]; a1.w += red[p + 3];
        a2.x += red[p + 4]; a2.y += red[p + 5]; a2.z += red[p + 6]; a2.w += red[p + 7];
        atomicAdd(&wf[c * 4],     a1.x);
        atomicAdd(&wf[c * 4 + 1], a1.y);
        atomicAdd(&wf[c * 4 + 2], a1.z);
        atomicAdd(&wf[c * 4 + 3], a1.w);
        atomicAdd(&wf[IN_DIM + c * 4],     a2.x);
        atomicAdd(&wf[IN_DIM + c * 4 + 1], a2.y);
        atomicAdd(&wf[IN_DIM + c * 4 + 2], a2.z);
        atomicAdd(&wf[IN_DIM + c * 4 + 3], a2.w);
    }
}

// ---------------------------------------------------------------------------
// Fused small chain: cpre -> v -> u, kc (grid barriers). 128 blocks x 128.
// ---------------------------------------------------------------------------
__global__ __launch_bounds__(128) void chain_kernel(
    const float* __restrict__ W1, const float* __restrict__ W2,
    const float* __restrict__ Wb, const float* __restrict__ b1,
    const float* __restrict__ b2, const float* __restrict__ bb,
    const float* __restrict__ wf, float* __restrict__ cpre,
    float* __restrict__ v, float* __restrict__ u, float* __restrict__ kc,
    int* __restrict__ bar, float inv_n)
{
    cudaGridDependencySynchronize();             // PDL: wait on wf
    int b = blockIdx.x;          // 0..127
    int t = threadIdx.x;         // 0..127
    int warp = t >> 5, lane = t & 31;

    {
        int hh = b >> 6, chunk = b & 63;
        const float* W = hh ? W2 : W1;
        const float* w = wf + hh * IN_DIM + chunk * 8;
        const float* Wc = W + (size_t)(chunk * 8) * OUT_DIM + t;
        float s = 0.f;
        #pragma unroll
        for (int k = 0; k < 8; k++)
            s += __ldg(&w[k]) * __ldg(&Wc[k * OUT_DIM]);
        atomicAdd(&cpre[hh * OUT_DIM + t], s);
    }
    grid_bar(&bar[0], 128);

    if (b < 64) {
        int gw = b * 4 + warp;
        int half = gw >> 7, d = gw & 127;
        const float* bh = half ? b2 : b1;
        const float* cp = cpre + half * OUT_DIM;
        const float* wr = Wb + (size_t)d * OUT_DIM;
        float s = 0.f;
        #pragma unroll
        for (int j = 0; j < 4; j++) {
            int e = lane + 32 * j;
            float c = 1.0f / (1.0f + expf(-(__ldcg(&cp[e]) * inv_n + __ldg(&bh[e]))));
            s += __ldg(&wr[e]) * c;
        }
        #pragma unroll
        for (int o = 16; o; o >>= 1) s += __shfl_xor_sync(0xffffffffu, s, o);
        if (lane == 0) v[half * OUT_DIM + d] = s;
    }
    grid_bar(&bar[1], 128);

    int W512 = b * 4 + warp;     // 0..511
    #pragma unroll
    for (int rep = 0; rep < 2; rep++) {
        int idx = W512 + rep * 512;
        int half = idx >> 9;                 // 0: u_a (W2,v1)  1: u_b (W1,v2)
        int tt = idx & 511;
        const float* W = half ? W1 : W2;
        const float* vv = v + half * OUT_DIM;
        const float* wr = W + (size_t)tt * OUT_DIM;
        float s = 0.f;
        #pragma unroll
        for (int j = 0; j < 4; j++) {
            int d = lane + 32 * j;
            s += __ldg(&wr[d]) * __ldcg(&vv[d]);
        }
        #pragma unroll
        for (int o = 16; o; o >>= 1) s += __shfl_xor_sync(0xffffffffu, s, o);
        if (lane == 0) u[half * IN_DIM + tt] = s;
    }
    if (W512 < 2) {                          // kc[0]=b2.v1+bb, kc[1]=b1.v2+bb
        const float* bv = W512 ? b1 : b2;
        const float* vv = v + W512 * OUT_DIM;
        float s = 0.f;
        #pragma unroll
        for (int j = 0; j < 4; j++) {
            int d = lane + 32 * j;
            s += __ldg(&bv[d]) * __ldcg(&vv[d]);
        }
        #pragma unroll
        for (int o = 16; o; o >>= 1) s += __shfl_xor_sync(0xffffffffu, s, o);
        if (lane == 0) kc[W512] = s + __ldg(bb);
    }
}

// ---------------------------------------------------------------------------
// p GEMVs over feat and shuf, writing interleaved p4 = (pfa,pfb,psa,psb).
// feat rows processed in REVERSE order: wf streamed feat low->high, so the
// high-v tail (~120MB) is still L2-resident; consume it first (LRU-friendly).
// ---------------------------------------------------------------------------
__global__ __launch_bounds__(512) void p_both_kernel(
    const float* __restrict__ feat, const float* __restrict__ shuf,
    const float* __restrict__ u, float4* __restrict__ p4, int n)
{
    __shared__ __align__(16) float su[2 * IN_DIM];
    cudaGridDependencySynchronize();             // PDL: wait on chain (u)
    for (int i = threadIdx.x; i < 2 * IN_DIM; i += 512) su[i] = u[i];
    __syncthreads();

    int warp = threadIdx.x >> 5, lane = threadIdx.x & 31;
    int idx = blockIdx.x * 16 + warp;          // 0 .. 2n-1
    if (idx >= 2 * n) return;
    const float* X;
    int v;
    int is_shuf;
    if (idx < n) { X = feat; v = n - 1 - idx; is_shuf = 0; }   // reverse
    else         { X = shuf; v = idx - n;     is_shuf = 1; }

    const float4* x4 = (const float4*)(X + (size_t)v * IN_DIM);
    const float4* ua4 = (const float4*)su;
    const float4* ub4 = (const float4*)(su + IN_DIM);
    float sa = 0.f, sb = 0.f;
    #pragma unroll
    for (int j = 0; j < 4; j++) {
        float4 x = x4[lane + 32 * j];
        float4 a = ua4[lane + 32 * j];
        float4 b = ub4[lane + 32 * j];
        sa += x.x * a.x + x.y * a.y + x.z * a.z + x.w * a.w;
        sb += x.x * b.x + x.y * b.y + x.z * b.z + x.w * b.w;
    }
    #pragma unroll
    for (int o = 16; o; o >>= 1) {
        sa += __shfl_xor_sync(0xffffffffu, sa, o);
        sb += __shfl_xor_sync(0xffffffffu, sb, o);
    }
    if (lane == 0) {
        float2* dst = (float2*)&p4[v] + is_shuf;   // .xy or .zw
        *dst = make_float2(sa, sb);
    }
}

// ---------------------------------------------------------------------------
// Scatter with v2 reductions.
//   blockIdx.y 0: list2 -> accA (q0,q2) ;  1: list1 -> accB (q1,q3)
// ---------------------------------------------------------------------------
__global__ __launch_bounds__(256) void scatter_v2_kernel(
    const int* __restrict__ src2, const int* __restrict__ dst2, int ne2,
    const int* __restrict__ src1, const int* __restrict__ dst1, int ne1,
    const float4* __restrict__ p4, float2* __restrict__ accA,
    float2* __restrict__ accB)
{
    cudaGridDependencySynchronize();             // PDL: wait on p
    const int* src; const int* dst; float2* acc; int ne; int sel;
    if (blockIdx.y == 0) { src = src2; dst = dst2; ne = ne2; acc = accA; sel = 0; }
    else                 { src = src1; dst = dst1; ne = ne1; acc = accB; sel = 1; }

    int e0 = (blockIdx.x * 256 + threadIdx.x) * 4;
    if (e0 + 3 < ne) {
        int4 s = *(const int4*)(src + e0);
        int4 d = *(const int4*)(dst + e0);
        float4 px = __ldg(&p4[s.x]);
        float4 py = __ldg(&p4[s.y]);
        float4 pz = __ldg(&p4[s.z]);
        float4 pw = __ldg(&p4[s.w]);
        if (sel == 0) {
            red_v2(&acc[d.x], px.x, px.z);
            red_v2(&acc[d.y], py.x, py.z);
            red_v2(&acc[d.z], pz.x, pz.z);
            red_v2(&acc[d.w], pw.x, pw.z);
        } else {
            red_v2(&acc[d.x], px.y, px.w);
            red_v2(&acc[d.y], py.y, py.w);
            red_v2(&acc[d.z], pz.y, pz.w);
            red_v2(&acc[d.w], pw.y, pw.w);
        }
    } else {
        for (int e = e0; e < ne; e++) {
            float4 pv = __ldg(&p4[src[e]]);
            if (sel == 0) red_v2(&acc[dst[e]], pv.x, pv.z);
            else          red_v2(&acc[dst[e]], pv.y, pv.w);
        }
    }
}

// ---------------------------------------------------------------------------
// Finalize: de-interleave acc into the four output quarters, add constants.
// ---------------------------------------------------------------------------
__global__ void finalize_kernel(const float2* __restrict__ accA,
                                const float2* __restrict__ accB,
                                const float* __restrict__ kc,
                                float* __restrict__ out, int n)
{
    cudaGridDependencySynchronize();             // PDL: wait on scatter
    int i = blockIdx.x * 256 + threadIdx.x;
    if (i < n) {
        float k1 = __ldg(&kc[0]), k2 = __ldg(&kc[1]);
        float2 a = accA[i];
        float2 b = accB[i];
        out[i]         = a.x + k1;   // sc1 = h2.v1
        out[n + i]     = b.x + k2;   // sc2 = h1.v2
        out[2 * n + i] = a.y + k1;   // sc3 = h4.v1
        out[3 * n + i] = b.y + k2;   // sc4 = h3.v2
    }
}

// ---------------------------------------------------------------------------
// PDL launch helper
// ---------------------------------------------------------------------------
template <typename K, typename... Args>
static void launch_pdl(dim3 grid, dim3 block, K kernel, Args... args)
{
    cudaLaunchConfig_t cfg = {};
    cfg.gridDim = grid;
    cfg.blockDim = block;
    cudaLaunchAttribute attr[1];
    attr[0].id = cudaLaunchAttributeProgrammaticStreamSerialization;
    attr[0].val.programmaticStreamSerializationAllowed = 1;
    cfg.attrs = attr;
    cfg.numAttrs = 1;
    cudaLaunchKernelEx(&cfg, kernel, args...);
}

// ---------------------------------------------------------------------------
// Launch
// ---------------------------------------------------------------------------
extern "C" void kernel_launch(void* const* d_in, const int* in_sizes, int n_in,
                              void* d_out, int out_size)
{
    const float* feat = (const float*)d_in[0];
    const float* shuf = (const float*)d_in[1];
    const int*   src1 = (const int*)d_in[2];
    const int*   dst1 = (const int*)d_in[3];
    const int*   src2 = (const int*)d_in[4];
    const int*   dst2 = (const int*)d_in[5];
    const float* W1   = (const float*)d_in[6];
    const float* b1   = (const float*)d_in[7];
    const float* W2   = (const float*)d_in[8];
    const float* b2   = (const float*)d_in[9];
    const float* Wb   = (const float*)d_in[10];
    const float* bb   = (const float*)d_in[11];
    float* out = (float*)d_out;

    const int n   = in_sizes[0] / IN_DIM;   // 100000
    const int ne1 = in_sizes[2];
    const int ne2 = in_sizes[4];

    void* p;
    cudaGetSymbolAddress(&p, g_zero);
    int*    deg  = (int*)p;
    float*  wf   = (float*)((int*)p + OFF_WF);
    float*  cpre = (float*)((int*)p + OFF_CPRE);
    int*    bar  = (int*)p + OFF_BAR;
    float2* accA = (float2*)((int*)p + OFF_ACC);
    float2* accB = accA + NN;
    cudaGetSymbolAddress(&p, g_v);  float* v  = (float*)p;
    cudaGetSymbolAddress(&p, g_u);  float* u  = (float*)p;
    cudaGetSymbolAddress(&p, g_k);  float* kc = (float*)p;
    cudaGetSymbolAddress(&p, g_p4); float4* p4 = (float4*)p;

    // 0) zero deg+wf+cpre+bar+acc (one ~2.4MB memset)
    cudaMemsetAsync(deg, 0, (size_t)ZERO_INTS * sizeof(int));

    // 1) out-degree histograms (both lists, one launch)
    int gp1 = (ne1 / 4 + 255) / 256, gp2 = (ne2 / 4 + 255) / 256;
    int gpm = gp1 > gp2 ? gp1 : gp2;
    launch_pdl(dim3(gpm, 2), dim3(256), hist_both, src1, ne1, src2, ne2, deg);

    // 2) weighted row-sums of feat
    launch_pdl(dim3(1024), dim3(256), wf_kernel, feat, deg, deg + NN, wf, n);

    // 3) fused tiny chain -> u, kc
    launch_pdl(dim3(128), dim3(128), chain_kernel,
               W1, W2, Wb, b1, b2, bb, wf, cpre, v, u, kc, bar,
               1.0f / (float)n);

    // 4) p projections for feat+shuf, interleaved p4 (feat reversed for L2)
    launch_pdl(dim3((2 * n + 15) / 16), dim3(512), p_both_kernel,
               feat, shuf, u, p4, n);

    // 5) scatter with v2 reductions (both lists, one launch)
    launch_pdl(dim3(gpm, 2), dim3(256), scatter_v2_kernel,
               src2, dst2, ne2, src1, dst1, ne1, p4, accA, accB);

    // 6) finalize: acc + k -> out quarters
    launch_pdl(dim3((n + 255) / 256), dim3(256), finalize_kernel,
               accA, accB, kc, out, n);
}

// round 17
// speedup vs baseline: 1.1015x; 1.0089x over previous
#include <cuda_runtime.h>
#include <cstdint>
#include <math.h>

#define NN      100000
#define IN_DIM  512
#define OUT_DIM 128

// ---------------------------------------------------------------------------
// Scratch. INVARIANT: g_zero is all-zero at kernel_launch entry.
//   - zero-initialized at module load (static init of __device__ globals)
//   - re-zeroed by finalize_kernel at the end of every call
// Layout: [0,2NN) int deg | 1024 f wf | 256 f cpre | 4 int bar | acc f2 x 2NN
// ---------------------------------------------------------------------------
#define OFF_WF   (2 * NN)
#define OFF_CPRE (2 * NN + 1024)
#define OFF_BAR  (2 * NN + 1024 + 256)
#define OFF_ACC  (2 * NN + 1024 + 256 + 4)      // 201284 ints; 16B-aligned*4
#define ZERO_INTS (OFF_ACC + 4 * NN)
__device__ __align__(16) int g_zero[ZERO_INTS];
__device__ float  g_v [2 * OUT_DIM];
__device__ float  g_u [2 * IN_DIM];
__device__ float  g_k [2];
__device__ float4 g_p4[NN];                      // (pfa, pfb, psa, psb)

// ---------------------------------------------------------------------------
// Grid barrier (counter zero per the scratch invariant)
// ---------------------------------------------------------------------------
__device__ __forceinline__ void grid_bar(int* cnt, int nblocks) {
    __threadfence();
    __syncthreads();
    if (threadIdx.x == 0) {
        atomicAdd(cnt, 1);
        while (*(volatile int*)cnt < nblocks) {}
    }
    __syncthreads();
}

// ---------------------------------------------------------------------------
// Vector reduction: addr[0] += a, addr[1] += b
// ---------------------------------------------------------------------------
__device__ __forceinline__ void red_v2(float2* addr, float a, float b) {
    asm volatile("red.global.add.v2.f32 [%0], {%1, %2};"
                 :: "l"(addr), "f"(a), "f"(b) : "memory");
}

// ---------------------------------------------------------------------------
// Histogram over both src lists (blockIdx.y selects list).
// PDL sync orders these atomics after the PREVIOUS launch in the stream
// (prior replay's finalize re-zeroing) — load-bearing for the invariant.
// ---------------------------------------------------------------------------
__global__ void hist_both(const int* __restrict__ srcA, int neA,
                          const int* __restrict__ srcB, int neB,
                          int* __restrict__ deg)
{
    cudaGridDependencySynchronize();
    const int* src = blockIdx.y ? srcB : srcA;
    int ne = blockIdx.y ? neB : neA;
    int* dg = deg + blockIdx.y * NN;
    int e0 = (blockIdx.x * blockDim.x + threadIdx.x) * 4;
    if (e0 + 3 < ne) {
        int4 s = *(const int4*)(src + e0);
        atomicAdd(&dg[s.x], 1);
        atomicAdd(&dg[s.y], 1);
        atomicAdd(&dg[s.z], 1);
        atomicAdd(&dg[s.w], 1);
    } else {
        for (int e = e0; e < ne; e++) atomicAdd(&dg[src[e]], 1);
    }
}

// ---------------------------------------------------------------------------
// wf[c] = sum_v deg1[v]*feat[v,c] ; wf[512+c] = sum_v deg2[v]*feat[v,c]
// ---------------------------------------------------------------------------
__global__ __launch_bounds__(256) void wf_kernel(
    const float* __restrict__ feat, const int* __restrict__ deg1,
    const int* __restrict__ deg2, float* __restrict__ wf, int n)
{
    __shared__ float red[256 * 8];
    cudaGridDependencySynchronize();             // PDL: wait on hist
    int t = threadIdx.x;
    int half = t >> 7, c = t & 127;
    const float4* f4 = (const float4*)feat;

    float4 a1 = make_float4(0.f, 0.f, 0.f, 0.f);
    float4 a2 = make_float4(0.f, 0.f, 0.f, 0.f);
    for (int v = blockIdx.x * 2 + half; v < n; v += gridDim.x * 2) {
        float w1 = (float)__ldg(&deg1[v]);
        float w2 = (float)__ldg(&deg2[v]);
        float4 x = __ldg(&f4[(size_t)v * 128 + c]);
        a1.x += w1 * x.x; a1.y += w1 * x.y; a1.z += w1 * x.z; a1.w += w1 * x.w;
        a2.x += w2 * x.x; a2.y += w2 * x.y; a2.z += w2 * x.z; a2.w += w2 * x.w;
    }
    *(float4*)&red[t * 8]     = a1;
    *(float4*)&red[t * 8 + 4] = a2;
    __syncthreads();
    if (half == 0) {
        int p = (t + 128) * 8;
        a1.x += red[p];     a1.y += red[p + 1]; a1.z += red[p + 2]; a1.w += red[p + 3];
        a2.x += red[p + 4]; a2.y += red[p + 5]; a2.z += red[p + 6]; a2.w += red[p + 7];
        atomicAdd(&wf[c * 4],     a1.x);
        atomicAdd(&wf[c * 4 + 1], a1.y);
        atomicAdd(&wf[c * 4 + 2], a1.z);
        atomicAdd(&wf[c * 4 + 3], a1.w);
        atomicAdd(&wf[IN_DIM + c * 4],     a2.x);
        atomicAdd(&wf[IN_DIM + c * 4 + 1], a2.y);
        atomicAdd(&wf[IN_DIM + c * 4 + 2], a2.z);
        atomicAdd(&wf[IN_DIM + c * 4 + 3], a2.w);
    }
}

// ---------------------------------------------------------------------------
// Fused small chain: cpre -> v -> u, kc (grid barriers). 128 blocks x 128.
// ---------------------------------------------------------------------------
__global__ __launch_bounds__(128) void chain_kernel(
    const float* __restrict__ W1, const float* __restrict__ W2,
    const float* __restrict__ Wb, const float* __restrict__ b1,
    const float* __restrict__ b2, const float* __restrict__ bb,
    const float* __restrict__ wf, float* __restrict__ cpre,
    float* __restrict__ v, float* __restrict__ u, float* __restrict__ kc,
    int* __restrict__ bar, float inv_n)
{
    cudaGridDependencySynchronize();             // PDL: wait on wf
    int b = blockIdx.x;          // 0..127
    int t = threadIdx.x;         // 0..127
    int warp = t >> 5, lane = t & 31;

    {
        int hh = b >> 6, chunk = b & 63;
        const float* W = hh ? W2 : W1;
        const float* w = wf + hh * IN_DIM + chunk * 8;
        const float* Wc = W + (size_t)(chunk * 8) * OUT_DIM + t;
        float s = 0.f;
        #pragma unroll
        for (int k = 0; k < 8; k++)
            s += __ldg(&w[k]) * __ldg(&Wc[k * OUT_DIM]);
        atomicAdd(&cpre[hh * OUT_DIM + t], s);
    }
    grid_bar(&bar[0], 128);

    if (b < 64) {
        int gw = b * 4 + warp;
        int half = gw >> 7, d = gw & 127;
        const float* bh = half ? b2 : b1;
        const float* cp = cpre + half * OUT_DIM;
        const float* wr = Wb + (size_t)d * OUT_DIM;
        float s = 0.f;
        #pragma unroll
        for (int j = 0; j < 4; j++) {
            int e = lane + 32 * j;
            float c = 1.0f / (1.0f + expf(-(__ldcg(&cp[e]) * inv_n + __ldg(&bh[e]))));
            s += __ldg(&wr[e]) * c;
        }
        #pragma unroll
        for (int o = 16; o; o >>= 1) s += __shfl_xor_sync(0xffffffffu, s, o);
        if (lane == 0) v[half * OUT_DIM + d] = s;
    }
    grid_bar(&bar[1], 128);

    int W512 = b * 4 + warp;     // 0..511
    #pragma unroll
    for (int rep = 0; rep < 2; rep++) {
        int idx = W512 + rep * 512;
        int half = idx >> 9;                 // 0: u_a (W2,v1)  1: u_b (W1,v2)
        int tt = idx & 511;
        const float* W = half ? W1 : W2;
        const float* vv = v + half * OUT_DIM;
        const float* wr = W + (size_t)tt * OUT_DIM;
        float s = 0.f;
        #pragma unroll
        for (int j = 0; j < 4; j++) {
            int d = lane + 32 * j;
            s += __ldg(&wr[d]) * __ldcg(&vv[d]);
        }
        #pragma unroll
        for (int o = 16; o; o >>= 1) s += __shfl_xor_sync(0xffffffffu, s, o);
        if (lane == 0) u[half * IN_DIM + tt] = s;
    }
    if (W512 < 2) {                          // kc[0]=b2.v1+bb, kc[1]=b1.v2+bb
        const float* bv = W512 ? b1 : b2;
        const float* vv = v + W512 * OUT_DIM;
        float s = 0.f;
        #pragma unroll
        for (int j = 0; j < 4; j++) {
            int d = lane + 32 * j;
            s += __ldg(&bv[d]) * __ldcg(&vv[d]);
        }
        #pragma unroll
        for (int o = 16; o; o >>= 1) s += __shfl_xor_sync(0xffffffffu, s, o);
        if (lane == 0) kc[W512] = s + __ldg(bb);
    }
}

// ---------------------------------------------------------------------------
// p GEMVs over feat and shuf, writing interleaved p4 = (pfa,pfb,psa,psb).
// feat rows processed in REVERSE order (L2 tail reuse from wf).
// ---------------------------------------------------------------------------
__global__ __launch_bounds__(512) void p_both_kernel(
    const float* __restrict__ feat, const float* __restrict__ shuf,
    const float* __restrict__ u, float4* __restrict__ p4, int n)
{
    __shared__ __align__(16) float su[2 * IN_DIM];
    cudaGridDependencySynchronize();             // PDL: wait on chain (u)
    for (int i = threadIdx.x; i < 2 * IN_DIM; i += 512) su[i] = u[i];
    __syncthreads();

    int warp = threadIdx.x >> 5, lane = threadIdx.x & 31;
    int idx = blockIdx.x * 16 + warp;          // 0 .. 2n-1
    if (idx >= 2 * n) return;
    const float* X;
    int v;
    int is_shuf;
    if (idx < n) { X = feat; v = n - 1 - idx; is_shuf = 0; }   // reverse
    else         { X = shuf; v = idx - n;     is_shuf = 1; }

    const float4* x4 = (const float4*)(X + (size_t)v * IN_DIM);
    const float4* ua4 = (const float4*)su;
    const float4* ub4 = (const float4*)(su + IN_DIM);
    float sa = 0.f, sb = 0.f;
    #pragma unroll
    for (int j = 0; j < 4; j++) {
        float4 x = x4[lane + 32 * j];
        float4 a = ua4[lane + 32 * j];
        float4 b = ub4[lane + 32 * j];
        sa += x.x * a.x + x.y * a.y + x.z * a.z + x.w * a.w;
        sb += x.x * b.x + x.y * b.y + x.z * b.z + x.w * b.w;
    }
    #pragma unroll
    for (int o = 16; o; o >>= 1) {
        sa += __shfl_xor_sync(0xffffffffu, sa, o);
        sb += __shfl_xor_sync(0xffffffffu, sb, o);
    }
    if (lane == 0) {
        float2* dst = (float2*)&p4[v] + is_shuf;   // .xy or .zw
        *dst = make_float2(sa, sb);
    }
}

// ---------------------------------------------------------------------------
// Scatter with v2 reductions.
//   blockIdx.y 0: list2 -> accA (q0,q2) ;  1: list1 -> accB (q1,q3)
// ---------------------------------------------------------------------------
__global__ __launch_bounds__(256) void scatter_v2_kernel(
    const int* __restrict__ src2, const int* __restrict__ dst2, int ne2,
    const int* __restrict__ src1, const int* __restrict__ dst1, int ne1,
    const float4* __restrict__ p4, float2* __restrict__ accA,
    float2* __restrict__ accB)
{
    cudaGridDependencySynchronize();             // PDL: wait on p
    const int* src; const int* dst; float2* acc; int ne; int sel;
    if (blockIdx.y == 0) { src = src2; dst = dst2; ne = ne2; acc = accA; sel = 0; }
    else                 { src = src1; dst = dst1; ne = ne1; acc = accB; sel = 1; }

    int e0 = (blockIdx.x * 256 + threadIdx.x) * 4;
    if (e0 + 3 < ne) {
        int4 s = *(const int4*)(src + e0);
        int4 d = *(const int4*)(dst + e0);
        float4 px = __ldg(&p4[s.x]);
        float4 py = __ldg(&p4[s.y]);
        float4 pz = __ldg(&p4[s.z]);
        float4 pw = __ldg(&p4[s.w]);
        if (sel == 0) {
            red_v2(&acc[d.x], px.x, px.z);
            red_v2(&acc[d.y], py.x, py.z);
            red_v2(&acc[d.z], pz.x, pz.z);
            red_v2(&acc[d.w], pw.x, pw.z);
        } else {
            red_v2(&acc[d.x], px.y, px.w);
            red_v2(&acc[d.y], py.y, py.w);
            red_v2(&acc[d.z], pz.y, pz.w);
            red_v2(&acc[d.w], pw.y, pw.w);
        }
    } else {
        for (int e = e0; e < ne; e++) {
            float4 pv = __ldg(&p4[src[e]]);
            if (sel == 0) red_v2(&acc[dst[e]], pv.x, pv.z);
            else          red_v2(&acc[dst[e]], pv.y, pv.w);
        }
    }
}

// ---------------------------------------------------------------------------
// Finalize: acc + k -> out quarters, THEN restore the all-zero invariant:
//   - each thread zeroes the acc entries it just read (thread-owned, no race)
//   - grid-stride zero over [0, OFF_ACC) ints (deg/wf/cpre/bar): all of their
//     consumers (wf, chain) completed launches ago -> safe.
// ---------------------------------------------------------------------------
__global__ __launch_bounds__(256) void finalize_kernel(
    float2* __restrict__ accA, float2* __restrict__ accB,
    const float* __restrict__ kc, float* __restrict__ out,
    int* __restrict__ zbase, int n)
{
    cudaGridDependencySynchronize();             // PDL: wait on scatter
    int i = blockIdx.x * 256 + threadIdx.x;
    if (i < n) {
        float k1 = __ldg(&kc[0]), k2 = __ldg(&kc[1]);
        float2 a = accA[i];
        float2 b = accB[i];
        out[i]         = a.x + k1;   // sc1 = h2.v1
        out[n + i]     = b.x + k2;   // sc2 = h1.v2
        out[2 * n + i] = a.y + k1;   // sc3 = h4.v1
        out[3 * n + i] = b.y + k2;   // sc4 = h3.v2
        accA[i] = make_float2(0.f, 0.f);         // zero own acc entries
        accB[i] = make_float2(0.f, 0.f);
    }
    // zero deg+wf+cpre+bar: OFF_ACC ints = OFF_ACC/4 int4 (divisible by 4)
    int4* z4 = (int4*)zbase;
    const int nz = OFF_ACC / 4;
    const int GSZ = gridDim.x * 256;
    int4 zero4 = make_int4(0, 0, 0, 0);
    for (int j = i; j < nz; j += GSZ) z4[j] = zero4;
}

// ---------------------------------------------------------------------------
// PDL launch helper
// ---------------------------------------------------------------------------
template <typename K, typename... Args>
static void launch_pdl(dim3 grid, dim3 block, K kernel, Args... args)
{
    cudaLaunchConfig_t cfg = {};
    cfg.gridDim = grid;
    cfg.blockDim = block;
    cudaLaunchAttribute attr[1];
    attr[0].id = cudaLaunchAttributeProgrammaticStreamSerialization;
    attr[0].val.programmaticStreamSerializationAllowed = 1;
    cfg.attrs = attr;
    cfg.numAttrs = 1;
    cudaLaunchKernelEx(&cfg, kernel, args...);
}

// ---------------------------------------------------------------------------
// Launch (6 graph nodes; no memset — finalize maintains the zero invariant)
// ---------------------------------------------------------------------------
extern "C" void kernel_launch(void* const* d_in, const int* in_sizes, int n_in,
                              void* d_out, int out_size)
{
    const float* feat = (const float*)d_in[0];
    const float* shuf = (const float*)d_in[1];
    const int*   src1 = (const int*)d_in[2];
    const int*   dst1 = (const int*)d_in[3];
    const int*   src2 = (const int*)d_in[4];
    const int*   dst2 = (const int*)d_in[5];
    const float* W1   = (const float*)d_in[6];
    const float* b1   = (const float*)d_in[7];
    const float* W2   = (const float*)d_in[8];
    const float* b2   = (const float*)d_in[9];
    const float* Wb   = (const float*)d_in[10];
    const float* bb   = (const float*)d_in[11];
    float* out = (float*)d_out;

    const int n   = in_sizes[0] / IN_DIM;   // 100000
    const int ne1 = in_sizes[2];
    const int ne2 = in_sizes[4];

    void* p;
    cudaGetSymbolAddress(&p, g_zero);
    int*    deg  = (int*)p;
    float*  wf   = (float*)((int*)p + OFF_WF);
    float*  cpre = (float*)((int*)p + OFF_CPRE);
    int*    bar  = (int*)p + OFF_BAR;
    float2* accA = (float2*)((int*)p + OFF_ACC);
    float2* accB = accA + NN;
    cudaGetSymbolAddress(&p, g_v);  float* v  = (float*)p;
    cudaGetSymbolAddress(&p, g_u);  float* u  = (float*)p;
    cudaGetSymbolAddress(&p, g_k);  float* kc = (float*)p;
    cudaGetSymbolAddress(&p, g_p4); float4* p4 = (float4*)p;

    // 1) out-degree histograms (both lists, one launch)
    int gp1 = (ne1 / 4 + 255) / 256, gp2 = (ne2 / 4 + 255) / 256;
    int gpm = gp1 > gp2 ? gp1 : gp2;
    launch_pdl(dim3(gpm, 2), dim3(256), hist_both, src1, ne1, src2, ne2, deg);

    // 2) weighted row-sums of feat
    launch_pdl(dim3(1024), dim3(256), wf_kernel, feat, deg, deg + NN, wf, n);

    // 3) fused tiny chain -> u, kc
    launch_pdl(dim3(128), dim3(128), chain_kernel,
               W1, W2, Wb, b1, b2, bb, wf, cpre, v, u, kc, bar,
               1.0f / (float)n);

    // 4) p projections for feat+shuf, interleaved p4 (feat reversed for L2)
    launch_pdl(dim3((2 * n + 15) / 16), dim3(512), p_both_kernel,
               feat, shuf, u, p4, n);

    // 5) scatter with v2 reductions (both lists, one launch)
    launch_pdl(dim3(gpm, 2), dim3(256), scatter_v2_kernel,
               src2, dst2, ne2, src1, dst1, ne1, p4, accA, accB);

    // 6) finalize: acc + k -> out quarters, then re-zero scratch
    launch_pdl(dim3((n + 255) / 256), dim3(256), finalize_kernel,
               accA, accB, kc, out, (int*)deg, n);
}